// round 4
// baseline (speedup 1.0000x reference)
#include <cuda_runtime.h>
#include <math.h>

typedef unsigned long long ull_t;

#define B_  4
#define S_  2048
#define D_  1024
#define H_  16
#define HD_ 64
#define M_  (B_*S_)   // 8192

// Scratch (allocation-free rule: __device__ globals)
__device__ float g_Q[(size_t)B_*H_*S_*HD_];
__device__ float g_K[(size_t)B_*H_*S_*HD_];
__device__ float g_V[(size_t)B_*H_*S_*HD_];
__device__ float g_O[(size_t)M_*D_];

// ---------- packed f32x2 helpers (Blackwell FFMA2) ----------
__device__ __forceinline__ void fma2(ull_t& d, ull_t a, ull_t b) {
    asm("fma.rn.f32x2 %0, %1, %2, %0;" : "+l"(d) : "l"(a), "l"(b));
}
__device__ __forceinline__ ull_t dup2(float x) {
    ull_t r; asm("mov.b64 %0, {%1, %1};" : "=l"(r) : "f"(x)); return r;
}
__device__ __forceinline__ ull_t pack2(float x, float y) {
    ull_t r; asm("mov.b64 %0, {%1, %2};" : "=l"(r) : "f"(x), "f"(y)); return r;
}
__device__ __forceinline__ ull_t mul2(ull_t a, ull_t b) {
    ull_t r; asm("mul.rn.f32x2 %0, %1, %2;" : "=l"(r) : "l"(a), "l"(b)); return r;
}
__device__ __forceinline__ float2 unpk2(ull_t a) {
    float2 r; asm("mov.b64 {%0, %1}, %2;" : "=f"(r.x), "=f"(r.y) : "l"(a)); return r;
}

// =====================================================================
// NT GEMM: C[m][n] = sum_k A[m][k]*W[n][k] (+bias)
// MODE 0: C is [M_, D_] row-major, add bias
// MODE 1: C written to [B, H, S, HD] layout (head split), no bias
// =====================================================================
template<int MODE>
__global__ __launch_bounds__(256, 2)
void gemm_nt_kernel(const float* __restrict__ A, const float* __restrict__ W,
                    const float* __restrict__ bias, float* __restrict__ C)
{
    const int K = D_;
    const int N = D_;
    const int BK = 16;

    __shared__ float As[16][132];
    __shared__ float Bs[16][132];

    int tid = threadIdx.x;
    int tx = tid & 15, ty = tid >> 4;
    int m0 = blockIdx.y * 128;
    int n0 = blockIdx.x * 128;

    int lrow = tid >> 2;          // 0..63
    int lk   = (tid & 3) << 2;    // 0,4,8,12

    const float* Ag = A + (size_t)(m0 + lrow) * K + lk;
    const float* Wg = W + (size_t)(n0 + lrow) * K + lk;

    ull_t acc[4][8];
    #pragma unroll
    for (int i = 0; i < 4; i++)
        #pragma unroll
        for (int j = 0; j < 8; j++) acc[i][j] = 0ull;

    // prologue prefetch of k-tile 0
    float4 ra0 = *(const float4*)(Ag);
    float4 ra1 = *(const float4*)(Ag + (size_t)64 * K);
    float4 rb0 = *(const float4*)(Wg);
    float4 rb1 = *(const float4*)(Wg + (size_t)64 * K);

    const int NKT = K / BK;  // 64
    for (int kt = 0; kt < NKT; kt++) {
        As[lk+0][lrow]    = ra0.x; As[lk+1][lrow]    = ra0.y;
        As[lk+2][lrow]    = ra0.z; As[lk+3][lrow]    = ra0.w;
        As[lk+0][lrow+64] = ra1.x; As[lk+1][lrow+64] = ra1.y;
        As[lk+2][lrow+64] = ra1.z; As[lk+3][lrow+64] = ra1.w;
        Bs[lk+0][lrow]    = rb0.x; Bs[lk+1][lrow]    = rb0.y;
        Bs[lk+2][lrow]    = rb0.z; Bs[lk+3][lrow]    = rb0.w;
        Bs[lk+0][lrow+64] = rb1.x; Bs[lk+1][lrow+64] = rb1.y;
        Bs[lk+2][lrow+64] = rb1.z; Bs[lk+3][lrow+64] = rb1.w;
        __syncthreads();

        if (kt + 1 < NKT) {   // prefetch next tile into registers
            const float* Ag2 = Ag + (kt + 1) * BK;
            const float* Wg2 = Wg + (kt + 1) * BK;
            ra0 = *(const float4*)(Ag2);
            ra1 = *(const float4*)(Ag2 + (size_t)64 * K);
            rb0 = *(const float4*)(Wg2);
            rb1 = *(const float4*)(Wg2 + (size_t)64 * K);
        }

        #pragma unroll
        for (int k = 0; k < BK; k++) {
            union { float4 f; ull_t u[2]; } a0, a1;
            a0.f = *(const float4*)&As[k][ty * 8];
            a1.f = *(const float4*)&As[k][ty * 8 + 4];
            float4 b0 = *(const float4*)&Bs[k][tx * 8];
            float4 b1 = *(const float4*)&Bs[k][tx * 8 + 4];
            ull_t av[4] = { a0.u[0], a0.u[1], a1.u[0], a1.u[1] };
            float bv[8] = { b0.x, b0.y, b0.z, b0.w, b1.x, b1.y, b1.z, b1.w };
            #pragma unroll
            for (int j = 0; j < 8; j++) {
                ull_t bb = dup2(bv[j]);
                #pragma unroll
                for (int i = 0; i < 4; i++) fma2(acc[i][j], av[i], bb);
            }
        }
        __syncthreads();
    }

    // unpack accumulators (pairs along m)
    float accf[8][8];
    #pragma unroll
    for (int i2 = 0; i2 < 4; i2++)
        #pragma unroll
        for (int j = 0; j < 8; j++) {
            float2 v = unpk2(acc[i2][j]);
            accf[2*i2][j]   = v.x;
            accf[2*i2+1][j] = v.y;
        }

    int nbase = n0 + tx * 8;
    if (MODE == 0) {
        float4 bb0 = *(const float4*)&bias[nbase];
        float4 bb1 = *(const float4*)&bias[nbase + 4];
        #pragma unroll
        for (int i = 0; i < 8; i++) {
            int m = m0 + ty * 8 + i;
            float4 o0 = make_float4(accf[i][0]+bb0.x, accf[i][1]+bb0.y,
                                    accf[i][2]+bb0.z, accf[i][3]+bb0.w);
            float4 o1 = make_float4(accf[i][4]+bb1.x, accf[i][5]+bb1.y,
                                    accf[i][6]+bb1.z, accf[i][7]+bb1.w);
            *(float4*)&C[(size_t)m * N + nbase]     = o0;
            *(float4*)&C[(size_t)m * N + nbase + 4] = o1;
        }
    } else {
        int h = nbase >> 6;      // 8 consecutive n stay within one head (8 | 64)
        int d = nbase & 63;
        #pragma unroll
        for (int i = 0; i < 8; i++) {
            int m = m0 + ty * 8 + i;
            int b = m >> 11, s = m & 2047;
            float* dst = &C[(((size_t)(b * H_ + h)) * S_ + s) * HD_ + d];
            *(float4*)dst       = make_float4(accf[i][0], accf[i][1], accf[i][2], accf[i][3]);
            *(float4*)(dst + 4) = make_float4(accf[i][4], accf[i][5], accf[i][6], accf[i][7]);
        }
    }
}

// =====================================================================
// Flash attention fp32: per (b,h), Q[2048,64] x K[2048,64] -> softmax -> xV
// Block: 64 query rows, streams 64-key tiles. 256 threads, 4x4 microtiles.
// =====================================================================
__global__ __launch_bounds__(256, 2)
void attn_kernel(const float* __restrict__ Q, const float* __restrict__ Kg,
                 const float* __restrict__ Vg, float* __restrict__ O)
{
    extern __shared__ float sm[];
    float* Qs = sm;            // [64][64]
    float* Ks = sm + 4096;     // [64][64]
    float* Vs = sm + 8192;     // [64][64]
    float* Ps = sm + 12288;    // [64][64]

    int tid = threadIdx.x;
    int tx = tid & 15, ty = tid >> 4;
    int bh = blockIdx.y;
    int q0 = blockIdx.x * 64;

    const float* Qb = Q + ((size_t)bh * S_ + q0) * HD_;
    const float* Kb = Kg + (size_t)bh * S_ * HD_;
    const float* Vb = Vg + (size_t)bh * S_ * HD_;

    #pragma unroll
    for (int it = 0; it < 4; it++) {
        int i = tid + it * 256;
        int r = i >> 4, c = (i & 15) << 2;
        *(float4*)&Qs[r * 64 + c] = *(const float4*)&Qb[r * HD_ + c];
    }

    ull_t acc[4][4];   // paired along key index (lo=even c, hi=odd c)
    #pragma unroll
    for (int i = 0; i < 4; i++)
        #pragma unroll
        for (int j = 0; j < 4; j++) acc[i][j] = 0ull;
    float mi[4] = { -1e30f, -1e30f, -1e30f, -1e30f };
    float li[4] = { 0.f, 0.f, 0.f, 0.f };

    for (int kb = 0; kb < S_ / 64; kb++) {
        const float* Kt = Kb + (size_t)kb * 64 * HD_;
        const float* Vt = Vb + (size_t)kb * 64 * HD_;

        __syncthreads();   // prev-iter PV reads of Vs/Ps done
        #pragma unroll
        for (int it = 0; it < 4; it++) {
            int i = tid + it * 256;
            int r = i >> 4, c = (i & 15) << 2;
            *(float4*)&Ks[r * 64 + c] = *(const float4*)&Kt[r * HD_ + c];
            *(float4*)&Vs[r * 64 + c] = *(const float4*)&Vt[r * HD_ + c];
        }
        __syncthreads();

        // ---- S = Q K^T (f32x2 pairs along d; per-lane rotation kills bank conflicts)
        ull_t s2[4][4];
        #pragma unroll
        for (int i = 0; i < 4; i++)
            #pragma unroll
            for (int j = 0; j < 4; j++) s2[i][j] = 0ull;

        #pragma unroll 4
        for (int dg = 0; dg < 16; dg++) {
            int dd = ((dg + tx) & 15) << 2;
            union { float4 f; ull_t u[2]; } qf[4], kf[4];
            #pragma unroll
            for (int i = 0; i < 4; i++) qf[i].f = *(const float4*)&Qs[(ty*4+i)*64 + dd];
            #pragma unroll
            for (int j = 0; j < 4; j++) kf[j].f = *(const float4*)&Ks[(tx*4+j)*64 + dd];
            #pragma unroll
            for (int i = 0; i < 4; i++)
                #pragma unroll
                for (int j = 0; j < 4; j++) {
                    fma2(s2[i][j], qf[i].u[0], kf[j].u[0]);
                    fma2(s2[i][j], qf[i].u[1], kf[j].u[1]);
                }
        }

        // ---- online softmax (row groups = 16 contiguous lanes)
        float p[4][4];
        #pragma unroll
        for (int i = 0; i < 4; i++) {
            float srow[4];
            #pragma unroll
            for (int j = 0; j < 4; j++) {
                float2 v = unpk2(s2[i][j]);
                srow[j] = (v.x + v.y) * 0.125f;   // 1/sqrt(64)
            }
            float rm = fmaxf(fmaxf(srow[0], srow[1]), fmaxf(srow[2], srow[3]));
            rm = fmaxf(rm, __shfl_xor_sync(0xffffffffu, rm, 1));
            rm = fmaxf(rm, __shfl_xor_sync(0xffffffffu, rm, 2));
            rm = fmaxf(rm, __shfl_xor_sync(0xffffffffu, rm, 4));
            rm = fmaxf(rm, __shfl_xor_sync(0xffffffffu, rm, 8));
            float mnew = fmaxf(mi[i], rm);
            float corr = __expf(mi[i] - mnew);
            mi[i] = mnew;
            float rs = 0.f;
            #pragma unroll
            for (int j = 0; j < 4; j++) { p[i][j] = __expf(srow[j] - mnew); rs += p[i][j]; }
            rs += __shfl_xor_sync(0xffffffffu, rs, 1);
            rs += __shfl_xor_sync(0xffffffffu, rs, 2);
            rs += __shfl_xor_sync(0xffffffffu, rs, 4);
            rs += __shfl_xor_sync(0xffffffffu, rs, 8);
            li[i] = li[i] * corr + rs;
            ull_t c2 = dup2(corr);
            #pragma unroll
            for (int j = 0; j < 4; j++) acc[i][j] = mul2(acc[i][j], c2);
        }
        #pragma unroll
        for (int i = 0; i < 4; i++)
            *(float4*)&Ps[(ty*4+i)*64 + tx*4] = make_float4(p[i][0], p[i][1], p[i][2], p[i][3]);
        __syncthreads();

        // ---- O += P V (f32x2 pairs along c)
        #pragma unroll 4
        for (int cg = 0; cg < 16; cg++) {
            int cc = ((cg + tx) & 15) << 2;
            union { float4 f; ull_t u[2]; } pf[4];
            #pragma unroll
            for (int i = 0; i < 4; i++) pf[i].f = *(const float4*)&Ps[(ty*4+i)*64 + cc];
            float4 v0 = *(const float4*)&Vs[(cc+0)*64 + tx*4];
            float4 v1 = *(const float4*)&Vs[(cc+1)*64 + tx*4];
            float4 v2 = *(const float4*)&Vs[(cc+2)*64 + tx*4];
            float4 v3 = *(const float4*)&Vs[(cc+3)*64 + tx*4];
            ull_t va[4] = { pack2(v0.x,v1.x), pack2(v0.y,v1.y), pack2(v0.z,v1.z), pack2(v0.w,v1.w) };
            ull_t vb[4] = { pack2(v2.x,v3.x), pack2(v2.y,v3.y), pack2(v2.z,v3.z), pack2(v2.w,v3.w) };
            #pragma unroll
            for (int i = 0; i < 4; i++)
                #pragma unroll
                for (int j = 0; j < 4; j++) {
                    fma2(acc[i][j], pf[i].u[0], va[j]);
                    fma2(acc[i][j], pf[i].u[1], vb[j]);
                }
        }
    }

    // epilogue: normalize + write [B,S,D]
    int b = bh >> 4, h = bh & 15;
    #pragma unroll
    for (int i = 0; i < 4; i++) {
        float inv = 1.0f / li[i];
        int s = q0 + ty * 4 + i;
        float o[4];
        #pragma unroll
        for (int j = 0; j < 4; j++) {
            float2 v = unpk2(acc[i][j]);
            o[j] = (v.x + v.y) * inv;
        }
        *(float4*)&O[((size_t)(b * S_ + s)) * D_ + h * HD_ + tx * 4] =
            make_float4(o[0], o[1], o[2], o[3]);
    }
}

// =====================================================================
extern "C" void kernel_launch(void* const* d_in, const int* in_sizes, int n_in,
                              void* d_out, int out_size)
{
    const float* query = (const float*)d_in[0];
    const float* key   = (const float*)d_in[1];
    const float* value = (const float*)d_in[2];
    const float* wq    = (const float*)d_in[3];
    const float* wk    = (const float*)d_in[4];
    const float* wv    = (const float*)d_in[5];
    const float* wo    = (const float*)d_in[6];
    const float* bo    = (const float*)d_in[7];
    float* out = (float*)d_out;

    float *Qp, *Kp, *Vp, *Op;
    cudaGetSymbolAddress((void**)&Qp, g_Q);
    cudaGetSymbolAddress((void**)&Kp, g_K);
    cudaGetSymbolAddress((void**)&Vp, g_V);
    cudaGetSymbolAddress((void**)&Op, g_O);

    cudaFuncSetAttribute(attn_kernel, cudaFuncAttributeMaxDynamicSharedMemorySize, 65536);

    dim3 gg(D_ / 128, M_ / 128);   // (8, 64)
    gemm_nt_kernel<1><<<gg, 256>>>(query, wq, nullptr, Qp);
    gemm_nt_kernel<1><<<gg, 256>>>(key,   wk, nullptr, Kp);
    gemm_nt_kernel<1><<<gg, 256>>>(value, wv, nullptr, Vp);

    attn_kernel<<<dim3(S_ / 64, B_ * H_), 256, 65536>>>(Qp, Kp, Vp, Op);

    gemm_nt_kernel<0><<<gg, 256>>>(Op, wo, bo, out);
}

// round 6
// speedup vs baseline: 1.2757x; 1.2757x over previous
#include <cuda_runtime.h>
#include <cuda_bf16.h>
#include <math.h>

typedef unsigned long long ull_t;
typedef unsigned int u32;

#define B_  4
#define S_  2048
#define D_  1024
#define H_  16
#define HD_ 64
#define M_  (B_*S_)   // 8192

// ---------------- scratch (__device__ globals: allocation-free rule) ----------
__device__ float g_Q[(size_t)B_*H_*S_*HD_];
__device__ float g_K[(size_t)B_*H_*S_*HD_];
__device__ float g_V[(size_t)B_*H_*S_*HD_];
__device__ __nv_bfloat16 g_Ah[(size_t)M_*D_];
__device__ __nv_bfloat16 g_Al[(size_t)M_*D_];
__device__ __nv_bfloat16 g_Wh[(size_t)D_*D_];
__device__ __nv_bfloat16 g_Wl[(size_t)D_*D_];
__device__ __nv_bfloat16 g_Oh[(size_t)M_*D_];
__device__ __nv_bfloat16 g_Ol[(size_t)M_*D_];

// ---------------- packed f32x2 helpers (attention kernel) --------------------
__device__ __forceinline__ void fma2(ull_t& d, ull_t a, ull_t b) {
    asm("fma.rn.f32x2 %0, %1, %2, %0;" : "+l"(d) : "l"(a), "l"(b));
}
__device__ __forceinline__ ull_t dup2(float x) {
    ull_t r; asm("mov.b64 %0, {%1, %1};" : "=l"(r) : "f"(x)); return r;
}
__device__ __forceinline__ ull_t pack2(float x, float y) {
    ull_t r; asm("mov.b64 %0, {%1, %2};" : "=l"(r) : "f"(x), "f"(y)); return r;
}
__device__ __forceinline__ ull_t mul2(ull_t a, ull_t b) {
    ull_t r; asm("mul.rn.f32x2 %0, %1, %2;" : "=l"(r) : "l"(a), "l"(b)); return r;
}
__device__ __forceinline__ float2 unpk2(ull_t a) {
    float2 r; asm("mov.b64 {%0, %1}, %2;" : "=f"(r.x), "=f"(r.y) : "l"(a)); return r;
}

// ---------------- baseline-PTX tensor-core helpers (sm_80+, works on sm_103) --
__device__ __forceinline__ u32 smem_u32(const void* p) {
    u32 a; asm("{ .reg .u64 t; cvta.to.shared.u64 t, %1; cvt.u32.u64 %0, t; }" : "=r"(a) : "l"(p));
    return a;
}
__device__ __forceinline__ void ldm_x4(u32* r, u32 addr) {
    asm volatile("ldmatrix.sync.aligned.m8n8.x4.shared.b16 {%0,%1,%2,%3}, [%4];"
        : "=r"(r[0]), "=r"(r[1]), "=r"(r[2]), "=r"(r[3]) : "r"(addr));
}
__device__ __forceinline__ void mma16816(float* d, const u32* a, u32 b0, u32 b1) {
    asm volatile("mma.sync.aligned.m16n8k16.row.col.f32.bf16.bf16.f32 "
        "{%0,%1,%2,%3}, {%4,%5,%6,%7}, {%8,%9}, {%0,%1,%2,%3};"
        : "+f"(d[0]), "+f"(d[1]), "+f"(d[2]), "+f"(d[3])
        : "r"(a[0]), "r"(a[1]), "r"(a[2]), "r"(a[3]), "r"(b0), "r"(b1));
}
#define CP_ASYNC(dst, src) asm volatile("cp.async.cg.shared.global [%0], [%1], 16;" :: "r"(dst), "l"(src) : "memory")
#define CP_COMMIT()  asm volatile("cp.async.commit_group;" ::: "memory")
#define CP_WAIT(n)   asm volatile("cp.async.wait_group %0;" :: "n"(n) : "memory")

// =====================================================================
// fp32 -> bf16 hi/lo split (x = hi + lo + O(2^-16 x))
// =====================================================================
__global__ void split_bf16_kernel(const float* __restrict__ x,
                                  __nv_bfloat16* __restrict__ hi,
                                  __nv_bfloat16* __restrict__ lo, int n4)
{
    int i = blockIdx.x * blockDim.x + threadIdx.x;
    if (i >= n4) return;
    float4 v = ((const float4*)x)[i];
    float f[4] = { v.x, v.y, v.z, v.w };
    union { __nv_bfloat16 b[4]; uint2 u; } Hh, Ll;
    #pragma unroll
    for (int j = 0; j < 4; j++) {
        __nv_bfloat16 h = __float2bfloat16(f[j]);
        Hh.b[j] = h;
        Ll.b[j] = __float2bfloat16(f[j] - __bfloat162float(h));
    }
    ((uint2*)hi)[i] = Hh.u;
    ((uint2*)lo)[i] = Ll.u;
}

// =====================================================================
// HMMA GEMM (mma.sync bf16, hi/lo 3-pass): C[m][n] = sum_k A[m][k]*W[n][k]
// CTA 128x128, 8 warps (2m x 4n), warp tile 64x32, k-chunk 32, cp.async DB.
// MODE 0: C=[M_,D_]+bias. MODE 1: C->[B,H,S,HD].
// =====================================================================
#define SROW 40                      // bf16 per smem row (32 data + 8 pad)
#define TILEB (128 * SROW * 2)       // 10240 B per tile
#define BUFB  (4 * TILEB)            // Ah,Al,Bh,Bl : 40960 B
#define GEMM_SMEM (2 * BUFB + 128)   // 82048 B

template<int MODE>
__global__ __launch_bounds__(256, 1)
void gemm_mm(const __nv_bfloat16* __restrict__ Ah, const __nv_bfloat16* __restrict__ Al,
             const __nv_bfloat16* __restrict__ Bh, const __nv_bfloat16* __restrict__ Bl,
             const float* __restrict__ bias, float* __restrict__ C)
{
    extern __shared__ char smem[];
    const u32 sbase = (smem_u32(smem) + 127) & ~127u;

    const int t = threadIdx.x;
    const int l = t & 31;
    const int warp = t >> 5;
    const int wm = warp >> 2, wn = warp & 3;
    const int m0 = blockIdx.y * 128;
    const int n0 = blockIdx.x * 128;

    const __nv_bfloat16* gp0 = Ah + (size_t)m0 * D_;
    const __nv_bfloat16* gp1 = Al + (size_t)m0 * D_;
    const __nv_bfloat16* gp2 = Bh + (size_t)n0 * D_;
    const __nv_bfloat16* gp3 = Bl + (size_t)n0 * D_;

    // per-lane ldmatrix offsets
    const u32 aoff = ((u32)(wm*64 + ((l & 7) + ((l >> 3) & 1) * 8)) * SROW + ((l >> 4) * 8)) * 2;
    const u32 boff = ((u32)(wn*32 + ((l & 7) + ((l >> 4) & 1) * 8)) * SROW + (((l >> 3) & 1) * 8)) * 2;

    float acc[4][4][4];
    #pragma unroll
    for (int i = 0; i < 4; i++)
        #pragma unroll
        for (int j = 0; j < 4; j++)
            #pragma unroll
            for (int q = 0; q < 4; q++) acc[i][j][q] = 0.f;

    const int r_ld = (t + 0) >> 2;      // base row for this thread's copies
    const int c_ld = t & 3;

    // chunk copy: 4 tiles x 128 rows x 64B ; thread does 8 x 16B cp.async
    auto cp_chunk = [&](int kc, int bufsel) {
        u32 db = sbase + (u32)bufsel * BUFB;
        #pragma unroll
        for (int i = 0; i < 8; i++) {
            int idx = t + (i & 1) * 256;        // 0..511 within tile
            int r = idx >> 2, c = idx & 3;
            size_t go = (size_t)r * D_ + kc + c * 8;
            u32 dst = db + (u32)(i >> 1) * TILEB + (u32)(r * SROW + c * 8) * 2;
            const __nv_bfloat16* src = (i < 2) ? gp0 : (i < 4) ? gp1 : (i < 6) ? gp2 : gp3;
            CP_ASYNC(dst, src + go);
        }
    };
    (void)r_ld; (void)c_ld;

    cp_chunk(0, 0);
    CP_COMMIT();

    const int NCH = D_ / 32;   // 32
    for (int kt = 0; kt < NCH; kt++) {
        int buf = kt & 1;
        if (kt + 1 < NCH) {
            cp_chunk((kt + 1) * 32, buf ^ 1);
            CP_COMMIT();
            CP_WAIT(1);
        } else {
            CP_WAIT(0);
        }
        __syncthreads();

        u32 aH = sbase + (u32)buf * BUFB;
        u32 bH = aH + 2 * TILEB;

        #pragma unroll
        for (int ks = 0; ks < 2; ks++) {
            u32 ah[4][4], al[4][4], bh[2][4], bl[2][4];
            #pragma unroll
            for (int mt = 0; mt < 4; mt++) {
                u32 ad = aH + aoff + (u32)(mt * 16 * SROW + ks * 16) * 2;
                ldm_x4(ah[mt], ad);
                ldm_x4(al[mt], ad + TILEB);
            }
            #pragma unroll
            for (int nt = 0; nt < 2; nt++) {
                u32 bd = bH + boff + (u32)(nt * 16 * SROW + ks * 16) * 2;
                ldm_x4(bh[nt], bd);
                ldm_x4(bl[nt], bd + TILEB);
            }
            #pragma unroll
            for (int mt = 0; mt < 4; mt++)
                #pragma unroll
                for (int j = 0; j < 4; j++) {
                    u32 h0 = bh[j >> 1][(j & 1) * 2], h1 = bh[j >> 1][(j & 1) * 2 + 1];
                    u32 l0 = bl[j >> 1][(j & 1) * 2], l1 = bl[j >> 1][(j & 1) * 2 + 1];
                    mma16816(acc[mt][j], ah[mt], h0, h1);   // Ah*Bh
                    mma16816(acc[mt][j], al[mt], h0, h1);   // Al*Bh
                    mma16816(acc[mt][j], ah[mt], l0, l1);   // Ah*Bl
                }
        }
        __syncthreads();
    }

    // epilogue: lane l holds rows (mt*16 + l/4, +8), cols (j*8 + (l%4)*2, +1)
    const int r0 = l >> 2, cp2 = (l & 3) * 2;
    #pragma unroll
    for (int mt = 0; mt < 4; mt++)
        #pragma unroll
        for (int j = 0; j < 4; j++) {
            int m = m0 + wm * 64 + mt * 16 + r0;
            int n = n0 + wn * 32 + j * 8 + cp2;
            if (MODE == 0) {
                float2 bb = *(const float2*)&bias[n];
                *(float2*)&C[(size_t)m * D_ + n] =
                    make_float2(acc[mt][j][0] + bb.x, acc[mt][j][1] + bb.y);
                *(float2*)&C[(size_t)(m + 8) * D_ + n] =
                    make_float2(acc[mt][j][2] + bb.x, acc[mt][j][3] + bb.y);
            } else {
                int h = n >> 6, d = n & 63;
                int b = m >> 11, s = m & 2047;
                float* dst = &C[(((size_t)(b * H_ + h)) * S_ + s) * HD_ + d];
                *(float2*)dst = make_float2(acc[mt][j][0], acc[mt][j][1]);
                *(float2*)(dst + 8 * HD_) = make_float2(acc[mt][j][2], acc[mt][j][3]);
            }
        }
}

// =====================================================================
// Flash attention fp32 (proven scalar core); epilogue writes bf16 hi/lo O
// =====================================================================
__global__ __launch_bounds__(256, 2)
void attn_kernel(const float* __restrict__ Q, const float* __restrict__ Kg,
                 const float* __restrict__ Vg,
                 __nv_bfloat16* __restrict__ Oh, __nv_bfloat16* __restrict__ Ol)
{
    extern __shared__ float sm[];
    float* Qs = sm;            // [64][64]
    float* Ks = sm + 4096;     // [64][64]
    float* Vs = sm + 8192;     // [64][64]
    float* Ps = sm + 12288;    // [64][64]

    int tid = threadIdx.x;
    int tx = tid & 15, ty = tid >> 4;
    int bh = blockIdx.y;
    int q0 = blockIdx.x * 64;

    const float* Qb = Q + ((size_t)bh * S_ + q0) * HD_;
    const float* Kb = Kg + (size_t)bh * S_ * HD_;
    const float* Vb = Vg + (size_t)bh * S_ * HD_;

    #pragma unroll
    for (int it = 0; it < 4; it++) {
        int i = tid + it * 256;
        int r = i >> 4, c = (i & 15) << 2;
        *(float4*)&Qs[r * 64 + c] = *(const float4*)&Qb[r * HD_ + c];
    }

    ull_t acc[4][4];
    #pragma unroll
    for (int i = 0; i < 4; i++)
        #pragma unroll
        for (int j = 0; j < 4; j++) acc[i][j] = 0ull;
    float mi[4] = { -1e30f, -1e30f, -1e30f, -1e30f };
    float li[4] = { 0.f, 0.f, 0.f, 0.f };

    for (int kb = 0; kb < S_ / 64; kb++) {
        const float* Kt = Kb + (size_t)kb * 64 * HD_;
        const float* Vt = Vb + (size_t)kb * 64 * HD_;

        __syncthreads();
        #pragma unroll
        for (int it = 0; it < 4; it++) {
            int i = tid + it * 256;
            int r = i >> 4, c = (i & 15) << 2;
            *(float4*)&Ks[r * 64 + c] = *(const float4*)&Kt[r * HD_ + c];
            *(float4*)&Vs[r * 64 + c] = *(const float4*)&Vt[r * HD_ + c];
        }
        __syncthreads();

        ull_t s2[4][4];
        #pragma unroll
        for (int i = 0; i < 4; i++)
            #pragma unroll
            for (int j = 0; j < 4; j++) s2[i][j] = 0ull;

        #pragma unroll 4
        for (int dg = 0; dg < 16; dg++) {
            int dd = ((dg + tx) & 15) << 2;
            union { float4 f; ull_t u[2]; } qf[4], kf[4];
            #pragma unroll
            for (int i = 0; i < 4; i++) qf[i].f = *(const float4*)&Qs[(ty*4+i)*64 + dd];
            #pragma unroll
            for (int j = 0; j < 4; j++) kf[j].f = *(const float4*)&Ks[(tx*4+j)*64 + dd];
            #pragma unroll
            for (int i = 0; i < 4; i++)
                #pragma unroll
                for (int j = 0; j < 4; j++) {
                    fma2(s2[i][j], qf[i].u[0], kf[j].u[0]);
                    fma2(s2[i][j], qf[i].u[1], kf[j].u[1]);
                }
        }

        float p[4][4];
        #pragma unroll
        for (int i = 0; i < 4; i++) {
            float srow[4];
            #pragma unroll
            for (int j = 0; j < 4; j++) {
                float2 v = unpk2(s2[i][j]);
                srow[j] = (v.x + v.y) * 0.125f;
            }
            float rm = fmaxf(fmaxf(srow[0], srow[1]), fmaxf(srow[2], srow[3]));
            rm = fmaxf(rm, __shfl_xor_sync(0xffffffffu, rm, 1));
            rm = fmaxf(rm, __shfl_xor_sync(0xffffffffu, rm, 2));
            rm = fmaxf(rm, __shfl_xor_sync(0xffffffffu, rm, 4));
            rm = fmaxf(rm, __shfl_xor_sync(0xffffffffu, rm, 8));
            float mnew = fmaxf(mi[i], rm);
            float corr = __expf(mi[i] - mnew);
            mi[i] = mnew;
            float rs = 0.f;
            #pragma unroll
            for (int j = 0; j < 4; j++) { p[i][j] = __expf(srow[j] - mnew); rs += p[i][j]; }
            rs += __shfl_xor_sync(0xffffffffu, rs, 1);
            rs += __shfl_xor_sync(0xffffffffu, rs, 2);
            rs += __shfl_xor_sync(0xffffffffu, rs, 4);
            rs += __shfl_xor_sync(0xffffffffu, rs, 8);
            li[i] = li[i] * corr + rs;
            ull_t c2 = dup2(corr);
            #pragma unroll
            for (int j = 0; j < 4; j++) acc[i][j] = mul2(acc[i][j], c2);
        }
        #pragma unroll
        for (int i = 0; i < 4; i++)
            *(float4*)&Ps[(ty*4+i)*64 + tx*4] = make_float4(p[i][0], p[i][1], p[i][2], p[i][3]);
        __syncthreads();

        #pragma unroll 4
        for (int cg = 0; cg < 16; cg++) {
            int cc = ((cg + tx) & 15) << 2;
            union { float4 f; ull_t u[2]; } pf[4];
            #pragma unroll
            for (int i = 0; i < 4; i++) pf[i].f = *(const float4*)&Ps[(ty*4+i)*64 + cc];
            float4 v0 = *(const float4*)&Vs[(cc+0)*64 + tx*4];
            float4 v1 = *(const float4*)&Vs[(cc+1)*64 + tx*4];
            float4 v2 = *(const float4*)&Vs[(cc+2)*64 + tx*4];
            float4 v3 = *(const float4*)&Vs[(cc+3)*64 + tx*4];
            ull_t va[4] = { pack2(v0.x,v1.x), pack2(v0.y,v1.y), pack2(v0.z,v1.z), pack2(v0.w,v1.w) };
            ull_t vb[4] = { pack2(v2.x,v3.x), pack2(v2.y,v3.y), pack2(v2.z,v3.z), pack2(v2.w,v3.w) };
            #pragma unroll
            for (int i = 0; i < 4; i++)
                #pragma unroll
                for (int j = 0; j < 4; j++) {
                    fma2(acc[i][j], pf[i].u[0], va[j]);
                    fma2(acc[i][j], pf[i].u[1], vb[j]);
                }
        }
    }

    // epilogue: normalize + write bf16 hi/lo into [M_, D_] layout
    int b = bh >> 4, h = bh & 15;
    #pragma unroll
    for (int i = 0; i < 4; i++) {
        float inv = 1.0f / li[i];
        int s = q0 + ty * 4 + i;
        size_t base = ((size_t)(b * S_ + s)) * D_ + h * HD_ + tx * 4;
        union { __nv_bfloat16 bb[4]; uint2 u; } HH, LL;
        #pragma unroll
        for (int j = 0; j < 4; j++) {
            float2 v = unpk2(acc[i][j]);
            float o = (v.x + v.y) * inv;
            __nv_bfloat16 hv = __float2bfloat16(o);
            HH.bb[j] = hv;
            LL.bb[j] = __float2bfloat16(o - __bfloat162float(hv));
        }
        *(uint2*)&Oh[base] = HH.u;
        *(uint2*)&Ol[base] = LL.u;
    }
}

// =====================================================================
extern "C" void kernel_launch(void* const* d_in, const int* in_sizes, int n_in,
                              void* d_out, int out_size)
{
    const float* query = (const float*)d_in[0];
    const float* key   = (const float*)d_in[1];
    const float* value = (const float*)d_in[2];
    const float* wq    = (const float*)d_in[3];
    const float* wk    = (const float*)d_in[4];
    const float* wv    = (const float*)d_in[5];
    const float* wo    = (const float*)d_in[6];
    const float* bo    = (const float*)d_in[7];
    float* out = (float*)d_out;

    float *Qp, *Kp, *Vp;
    __nv_bfloat16 *Ahp, *Alp, *Whp, *Wlp, *Ohp, *Olp;
    cudaGetSymbolAddress((void**)&Qp, g_Q);
    cudaGetSymbolAddress((void**)&Kp, g_K);
    cudaGetSymbolAddress((void**)&Vp, g_V);
    cudaGetSymbolAddress((void**)&Ahp, g_Ah);
    cudaGetSymbolAddress((void**)&Alp, g_Al);
    cudaGetSymbolAddress((void**)&Whp, g_Wh);
    cudaGetSymbolAddress((void**)&Wlp, g_Wl);
    cudaGetSymbolAddress((void**)&Ohp, g_Oh);
    cudaGetSymbolAddress((void**)&Olp, g_Ol);

    cudaFuncSetAttribute(gemm_mm<0>, cudaFuncAttributeMaxDynamicSharedMemorySize, GEMM_SMEM);
    cudaFuncSetAttribute(gemm_mm<1>, cudaFuncAttributeMaxDynamicSharedMemorySize, GEMM_SMEM);
    cudaFuncSetAttribute(attn_kernel, cudaFuncAttributeMaxDynamicSharedMemorySize, 65536);

    const int nAct4 = (M_ * D_) / 4;
    const int nW4   = (D_ * D_) / 4;
    dim3 gg(D_ / 128, M_ / 128);       // (8, 64)

    // Q projection
    split_bf16_kernel<<<nAct4 / 256, 256>>>(query, Ahp, Alp, nAct4);
    split_bf16_kernel<<<nW4 / 256, 256>>>(wq, Whp, Wlp, nW4);
    gemm_mm<1><<<gg, 256, GEMM_SMEM>>>(Ahp, Alp, Whp, Wlp, nullptr, Qp);
    // K projection
    split_bf16_kernel<<<nAct4 / 256, 256>>>(key, Ahp, Alp, nAct4);
    split_bf16_kernel<<<nW4 / 256, 256>>>(wk, Whp, Wlp, nW4);
    gemm_mm<1><<<gg, 256, GEMM_SMEM>>>(Ahp, Alp, Whp, Wlp, nullptr, Kp);
    // V projection
    split_bf16_kernel<<<nAct4 / 256, 256>>>(value, Ahp, Alp, nAct4);
    split_bf16_kernel<<<nW4 / 256, 256>>>(wv, Whp, Wlp, nW4);
    gemm_mm<1><<<gg, 256, GEMM_SMEM>>>(Ahp, Alp, Whp, Wlp, nullptr, Vp);

    // attention (writes bf16 hi/lo O)
    attn_kernel<<<dim3(S_ / 64, B_ * H_), 256, 65536>>>(Qp, Kp, Vp, Ohp, Olp);

    // output projection + bias
    split_bf16_kernel<<<nW4 / 256, 256>>>(wo, Whp, Wlp, nW4);
    gemm_mm<0><<<gg, 256, GEMM_SMEM>>>(Ohp, Olp, Whp, Wlp, bo, out);
}

// round 7
// speedup vs baseline: 1.2770x; 1.0010x over previous
#include <cuda_runtime.h>
#include <cuda_bf16.h>
#include <math.h>

typedef unsigned long long ull_t;
typedef unsigned int u32;

#define B_  4
#define S_  2048
#define D_  1024
#define H_  16
#define HD_ 64
#define M_  (B_*S_)   // 8192

// ---------------- scratch (__device__ globals: allocation-free rule) ----------
__device__ float g_Q[(size_t)B_*H_*S_*HD_];
__device__ float g_K[(size_t)B_*H_*S_*HD_];
__device__ float g_V[(size_t)B_*H_*S_*HD_];
__device__ __nv_bfloat16 g_Ah[(size_t)M_*D_];
__device__ __nv_bfloat16 g_Al[(size_t)M_*D_];
__device__ __nv_bfloat16 g_Wh[(size_t)D_*D_];
__device__ __nv_bfloat16 g_Wl[(size_t)D_*D_];
__device__ __nv_bfloat16 g_Oh[(size_t)M_*D_];
__device__ __nv_bfloat16 g_Ol[(size_t)M_*D_];

// ---------------- packed f32x2 helpers (attention kernel) --------------------
__device__ __forceinline__ void fma2(ull_t& d, ull_t a, ull_t b) {
    asm("fma.rn.f32x2 %0, %1, %2, %0;" : "+l"(d) : "l"(a), "l"(b));
}
__device__ __forceinline__ ull_t dup2(float x) {
    ull_t r; asm("mov.b64 %0, {%1, %1};" : "=l"(r) : "f"(x)); return r;
}
__device__ __forceinline__ ull_t pack2(float x, float y) {
    ull_t r; asm("mov.b64 %0, {%1, %2};" : "=l"(r) : "f"(x), "f"(y)); return r;
}
__device__ __forceinline__ ull_t mul2(ull_t a, ull_t b) {
    ull_t r; asm("mul.rn.f32x2 %0, %1, %2;" : "=l"(r) : "l"(a), "l"(b)); return r;
}
__device__ __forceinline__ float2 unpk2(ull_t a) {
    float2 r; asm("mov.b64 {%0, %1}, %2;" : "=f"(r.x), "=f"(r.y) : "l"(a)); return r;
}

// ---------------- baseline-PTX tensor-core helpers (sm_80+, works on sm_103) --
__device__ __forceinline__ u32 smem_u32(const void* p) {
    u32 a; asm("{ .reg .u64 t; cvta.to.shared.u64 t, %1; cvt.u32.u64 %0, t; }" : "=r"(a) : "l"(p));
    return a;
}
__device__ __forceinline__ void ldm_x4(u32* r, u32 addr) {
    asm volatile("ldmatrix.sync.aligned.m8n8.x4.shared.b16 {%0,%1,%2,%3}, [%4];"
        : "=r"(r[0]), "=r"(r[1]), "=r"(r[2]), "=r"(r[3]) : "r"(addr));
}
__device__ __forceinline__ void mma16816(float* d, const u32* a, u32 b0, u32 b1) {
    asm volatile("mma.sync.aligned.m16n8k16.row.col.f32.bf16.bf16.f32 "
        "{%0,%1,%2,%3}, {%4,%5,%6,%7}, {%8,%9}, {%0,%1,%2,%3};"
        : "+f"(d[0]), "+f"(d[1]), "+f"(d[2]), "+f"(d[3])
        : "r"(a[0]), "r"(a[1]), "r"(a[2]), "r"(a[3]), "r"(b0), "r"(b1));
}
#define CP_ASYNC(dst, src) asm volatile("cp.async.cg.shared.global [%0], [%1], 16;" :: "r"(dst), "l"(src) : "memory")
#define CP_COMMIT()  asm volatile("cp.async.commit_group;" ::: "memory")
#define CP_WAIT(n)   asm volatile("cp.async.wait_group %0;" :: "n"(n) : "memory")

// =====================================================================
// fp32 -> bf16 hi/lo split (x = hi + lo + O(2^-16 x))
// =====================================================================
__global__ void split_bf16_kernel(const float* __restrict__ x,
                                  __nv_bfloat16* __restrict__ hi,
                                  __nv_bfloat16* __restrict__ lo, int n4)
{
    int i = blockIdx.x * blockDim.x + threadIdx.x;
    if (i >= n4) return;
    float4 v = ((const float4*)x)[i];
    float f[4] = { v.x, v.y, v.z, v.w };
    union { __nv_bfloat16 b[4]; uint2 u; } Hh, Ll;
    #pragma unroll
    for (int j = 0; j < 4; j++) {
        __nv_bfloat16 h = __float2bfloat16(f[j]);
        Hh.b[j] = h;
        Ll.b[j] = __float2bfloat16(f[j] - __bfloat162float(h));
    }
    ((uint2*)hi)[i] = Hh.u;
    ((uint2*)lo)[i] = Ll.u;
}

// =====================================================================
// HMMA GEMM (mma.sync bf16, hi/lo 3-pass): C[m][n] = sum_k A[m][k]*W[n][k]
// CTA 128x128, 8 warps (2m x 4n), warp tile 64x32, k-chunk 32, cp.async DB.
// MODE 0: C=[M_,D_]+bias. MODE 1: C->[B,H,S,HD].
// =====================================================================
#define SROW 40                      // bf16 per smem row (32 data + 8 pad)
#define TILEB (128 * SROW * 2)       // 10240 B per tile
#define BUFB  (4 * TILEB)            // Ah,Al,Bh,Bl : 40960 B
#define GEMM_SMEM (2 * BUFB + 128)   // 82048 B

template<int MODE>
__global__ __launch_bounds__(256, 1)
void gemm_mm(const __nv_bfloat16* __restrict__ Ah, const __nv_bfloat16* __restrict__ Al,
             const __nv_bfloat16* __restrict__ Bh, const __nv_bfloat16* __restrict__ Bl,
             const float* __restrict__ bias, float* __restrict__ C)
{
    extern __shared__ char smem[];
    const u32 sbase = (smem_u32(smem) + 127) & ~127u;

    const int t = threadIdx.x;
    const int l = t & 31;
    const int warp = t >> 5;
    const int wm = warp >> 2, wn = warp & 3;
    const int m0 = blockIdx.y * 128;
    const int n0 = blockIdx.x * 128;

    const __nv_bfloat16* gp0 = Ah + (size_t)m0 * D_;
    const __nv_bfloat16* gp1 = Al + (size_t)m0 * D_;
    const __nv_bfloat16* gp2 = Bh + (size_t)n0 * D_;
    const __nv_bfloat16* gp3 = Bl + (size_t)n0 * D_;

    // per-lane ldmatrix offsets
    const u32 aoff = ((u32)(wm*64 + ((l & 7) + ((l >> 3) & 1) * 8)) * SROW + ((l >> 4) * 8)) * 2;
    const u32 boff = ((u32)(wn*32 + ((l & 7) + ((l >> 4) & 1) * 8)) * SROW + (((l >> 3) & 1) * 8)) * 2;

    float acc[4][4][4];
    #pragma unroll
    for (int i = 0; i < 4; i++)
        #pragma unroll
        for (int j = 0; j < 4; j++)
            #pragma unroll
            for (int q = 0; q < 4; q++) acc[i][j][q] = 0.f;

    const int r_ld = (t + 0) >> 2;      // base row for this thread's copies
    const int c_ld = t & 3;

    // chunk copy: 4 tiles x 128 rows x 64B ; thread does 8 x 16B cp.async
    auto cp_chunk = [&](int kc, int bufsel) {
        u32 db = sbase + (u32)bufsel * BUFB;
        #pragma unroll
        for (int i = 0; i < 8; i++) {
            int idx = t + (i & 1) * 256;        // 0..511 within tile
            int r = idx >> 2, c = idx & 3;
            size_t go = (size_t)r * D_ + kc + c * 8;
            u32 dst = db + (u32)(i >> 1) * TILEB + (u32)(r * SROW + c * 8) * 2;
            const __nv_bfloat16* src = (i < 2) ? gp0 : (i < 4) ? gp1 : (i < 6) ? gp2 : gp3;
            CP_ASYNC(dst, src + go);
        }
    };
    (void)r_ld; (void)c_ld;

    cp_chunk(0, 0);
    CP_COMMIT();

    const int NCH = D_ / 32;   // 32
    for (int kt = 0; kt < NCH; kt++) {
        int buf = kt & 1;
        if (kt + 1 < NCH) {
            cp_chunk((kt + 1) * 32, buf ^ 1);
            CP_COMMIT();
            CP_WAIT(1);
        } else {
            CP_WAIT(0);
        }
        __syncthreads();

        u32 aH = sbase + (u32)buf * BUFB;
        u32 bH = aH + 2 * TILEB;

        #pragma unroll
        for (int ks = 0; ks < 2; ks++) {
            u32 ah[4][4], al[4][4], bh[2][4], bl[2][4];
            #pragma unroll
            for (int mt = 0; mt < 4; mt++) {
                u32 ad = aH + aoff + (u32)(mt * 16 * SROW + ks * 16) * 2;
                ldm_x4(ah[mt], ad);
                ldm_x4(al[mt], ad + TILEB);
            }
            #pragma unroll
            for (int nt = 0; nt < 2; nt++) {
                u32 bd = bH + boff + (u32)(nt * 16 * SROW + ks * 16) * 2;
                ldm_x4(bh[nt], bd);
                ldm_x4(bl[nt], bd + TILEB);
            }
            #pragma unroll
            for (int mt = 0; mt < 4; mt++)
                #pragma unroll
                for (int j = 0; j < 4; j++) {
                    u32 h0 = bh[j >> 1][(j & 1) * 2], h1 = bh[j >> 1][(j & 1) * 2 + 1];
                    u32 l0 = bl[j >> 1][(j & 1) * 2], l1 = bl[j >> 1][(j & 1) * 2 + 1];
                    mma16816(acc[mt][j], ah[mt], h0, h1);   // Ah*Bh
                    mma16816(acc[mt][j], al[mt], h0, h1);   // Al*Bh
                    mma16816(acc[mt][j], ah[mt], l0, l1);   // Ah*Bl
                }
        }
        __syncthreads();
    }

    // epilogue: lane l holds rows (mt*16 + l/4, +8), cols (j*8 + (l%4)*2, +1)
    const int r0 = l >> 2, cp2 = (l & 3) * 2;
    #pragma unroll
    for (int mt = 0; mt < 4; mt++)
        #pragma unroll
        for (int j = 0; j < 4; j++) {
            int m = m0 + wm * 64 + mt * 16 + r0;
            int n = n0 + wn * 32 + j * 8 + cp2;
            if (MODE == 0) {
                float2 bb = *(const float2*)&bias[n];
                *(float2*)&C[(size_t)m * D_ + n] =
                    make_float2(acc[mt][j][0] + bb.x, acc[mt][j][1] + bb.y);
                *(float2*)&C[(size_t)(m + 8) * D_ + n] =
                    make_float2(acc[mt][j][2] + bb.x, acc[mt][j][3] + bb.y);
            } else {
                int h = n >> 6, d = n & 63;
                int b = m >> 11, s = m & 2047;
                float* dst = &C[(((size_t)(b * H_ + h)) * S_ + s) * HD_ + d];
                *(float2*)dst = make_float2(acc[mt][j][0], acc[mt][j][1]);
                *(float2*)(dst + 8 * HD_) = make_float2(acc[mt][j][2], acc[mt][j][3]);
            }
        }
}

// =====================================================================
// Flash attention fp32 (proven scalar core); epilogue writes bf16 hi/lo O
// =====================================================================
__global__ __launch_bounds__(256, 2)
void attn_kernel(const float* __restrict__ Q, const float* __restrict__ Kg,
                 const float* __restrict__ Vg,
                 __nv_bfloat16* __restrict__ Oh, __nv_bfloat16* __restrict__ Ol)
{
    extern __shared__ float sm[];
    float* Qs = sm;            // [64][64]
    float* Ks = sm + 4096;     // [64][64]
    float* Vs = sm + 8192;     // [64][64]
    float* Ps = sm + 12288;    // [64][64]

    int tid = threadIdx.x;
    int tx = tid & 15, ty = tid >> 4;
    int bh = blockIdx.y;
    int q0 = blockIdx.x * 64;

    const float* Qb = Q + ((size_t)bh * S_ + q0) * HD_;
    const float* Kb = Kg + (size_t)bh * S_ * HD_;
    const float* Vb = Vg + (size_t)bh * S_ * HD_;

    #pragma unroll
    for (int it = 0; it < 4; it++) {
        int i = tid + it * 256;
        int r = i >> 4, c = (i & 15) << 2;
        *(float4*)&Qs[r * 64 + c] = *(const float4*)&Qb[r * HD_ + c];
    }

    ull_t acc[4][4];
    #pragma unroll
    for (int i = 0; i < 4; i++)
        #pragma unroll
        for (int j = 0; j < 4; j++) acc[i][j] = 0ull;
    float mi[4] = { -1e30f, -1e30f, -1e30f, -1e30f };
    float li[4] = { 0.f, 0.f, 0.f, 0.f };

    for (int kb = 0; kb < S_ / 64; kb++) {
        const float* Kt = Kb + (size_t)kb * 64 * HD_;
        const float* Vt = Vb + (size_t)kb * 64 * HD_;

        __syncthreads();
        #pragma unroll
        for (int it = 0; it < 4; it++) {
            int i = tid + it * 256;
            int r = i >> 4, c = (i & 15) << 2;
            *(float4*)&Ks[r * 64 + c] = *(const float4*)&Kt[r * HD_ + c];
            *(float4*)&Vs[r * 64 + c] = *(const float4*)&Vt[r * HD_ + c];
        }
        __syncthreads();

        ull_t s2[4][4];
        #pragma unroll
        for (int i = 0; i < 4; i++)
            #pragma unroll
            for (int j = 0; j < 4; j++) s2[i][j] = 0ull;

        #pragma unroll 4
        for (int dg = 0; dg < 16; dg++) {
            int dd = ((dg + tx) & 15) << 2;
            union { float4 f; ull_t u[2]; } qf[4], kf[4];
            #pragma unroll
            for (int i = 0; i < 4; i++) qf[i].f = *(const float4*)&Qs[(ty*4+i)*64 + dd];
            #pragma unroll
            for (int j = 0; j < 4; j++) kf[j].f = *(const float4*)&Ks[(tx*4+j)*64 + dd];
            #pragma unroll
            for (int i = 0; i < 4; i++)
                #pragma unroll
                for (int j = 0; j < 4; j++) {
                    fma2(s2[i][j], qf[i].u[0], kf[j].u[0]);
                    fma2(s2[i][j], qf[i].u[1], kf[j].u[1]);
                }
        }

        float p[4][4];
        #pragma unroll
        for (int i = 0; i < 4; i++) {
            float srow[4];
            #pragma unroll
            for (int j = 0; j < 4; j++) {
                float2 v = unpk2(s2[i][j]);
                srow[j] = (v.x + v.y) * 0.125f;
            }
            float rm = fmaxf(fmaxf(srow[0], srow[1]), fmaxf(srow[2], srow[3]));
            rm = fmaxf(rm, __shfl_xor_sync(0xffffffffu, rm, 1));
            rm = fmaxf(rm, __shfl_xor_sync(0xffffffffu, rm, 2));
            rm = fmaxf(rm, __shfl_xor_sync(0xffffffffu, rm, 4));
            rm = fmaxf(rm, __shfl_xor_sync(0xffffffffu, rm, 8));
            float mnew = fmaxf(mi[i], rm);
            float corr = __expf(mi[i] - mnew);
            mi[i] = mnew;
            float rs = 0.f;
            #pragma unroll
            for (int j = 0; j < 4; j++) { p[i][j] = __expf(srow[j] - mnew); rs += p[i][j]; }
            rs += __shfl_xor_sync(0xffffffffu, rs, 1);
            rs += __shfl_xor_sync(0xffffffffu, rs, 2);
            rs += __shfl_xor_sync(0xffffffffu, rs, 4);
            rs += __shfl_xor_sync(0xffffffffu, rs, 8);
            li[i] = li[i] * corr + rs;
            ull_t c2 = dup2(corr);
            #pragma unroll
            for (int j = 0; j < 4; j++) acc[i][j] = mul2(acc[i][j], c2);
        }
        #pragma unroll
        for (int i = 0; i < 4; i++)
            *(float4*)&Ps[(ty*4+i)*64 + tx*4] = make_float4(p[i][0], p[i][1], p[i][2], p[i][3]);
        __syncthreads();

        #pragma unroll 4
        for (int cg = 0; cg < 16; cg++) {
            int cc = ((cg + tx) & 15) << 2;
            union { float4 f; ull_t u[2]; } pf[4];
            #pragma unroll
            for (int i = 0; i < 4; i++) pf[i].f = *(const float4*)&Ps[(ty*4+i)*64 + cc];
            float4 v0 = *(const float4*)&Vs[(cc+0)*64 + tx*4];
            float4 v1 = *(const float4*)&Vs[(cc+1)*64 + tx*4];
            float4 v2 = *(const float4*)&Vs[(cc+2)*64 + tx*4];
            float4 v3 = *(const float4*)&Vs[(cc+3)*64 + tx*4];
            ull_t va[4] = { pack2(v0.x,v1.x), pack2(v0.y,v1.y), pack2(v0.z,v1.z), pack2(v0.w,v1.w) };
            ull_t vb[4] = { pack2(v2.x,v3.x), pack2(v2.y,v3.y), pack2(v2.z,v3.z), pack2(v2.w,v3.w) };
            #pragma unroll
            for (int i = 0; i < 4; i++)
                #pragma unroll
                for (int j = 0; j < 4; j++) {
                    fma2(acc[i][j], pf[i].u[0], va[j]);
                    fma2(acc[i][j], pf[i].u[1], vb[j]);
                }
        }
    }

    // epilogue: normalize + write bf16 hi/lo into [M_, D_] layout
    int b = bh >> 4, h = bh & 15;
    #pragma unroll
    for (int i = 0; i < 4; i++) {
        float inv = 1.0f / li[i];
        int s = q0 + ty * 4 + i;
        size_t base = ((size_t)(b * S_ + s)) * D_ + h * HD_ + tx * 4;
        union { __nv_bfloat16 bb[4]; uint2 u; } HH, LL;
        #pragma unroll
        for (int j = 0; j < 4; j++) {
            float2 v = unpk2(acc[i][j]);
            float o = (v.x + v.y) * inv;
            __nv_bfloat16 hv = __float2bfloat16(o);
            HH.bb[j] = hv;
            LL.bb[j] = __float2bfloat16(o - __bfloat162float(hv));
        }
        *(uint2*)&Oh[base] = HH.u;
        *(uint2*)&Ol[base] = LL.u;
    }
}

// =====================================================================
extern "C" void kernel_launch(void* const* d_in, const int* in_sizes, int n_in,
                              void* d_out, int out_size)
{
    const float* query = (const float*)d_in[0];
    const float* key   = (const float*)d_in[1];
    const float* value = (const float*)d_in[2];
    const float* wq    = (const float*)d_in[3];
    const float* wk    = (const float*)d_in[4];
    const float* wv    = (const float*)d_in[5];
    const float* wo    = (const float*)d_in[6];
    const float* bo    = (const float*)d_in[7];
    float* out = (float*)d_out;

    float *Qp, *Kp, *Vp;
    __nv_bfloat16 *Ahp, *Alp, *Whp, *Wlp, *Ohp, *Olp;
    cudaGetSymbolAddress((void**)&Qp, g_Q);
    cudaGetSymbolAddress((void**)&Kp, g_K);
    cudaGetSymbolAddress((void**)&Vp, g_V);
    cudaGetSymbolAddress((void**)&Ahp, g_Ah);
    cudaGetSymbolAddress((void**)&Alp, g_Al);
    cudaGetSymbolAddress((void**)&Whp, g_Wh);
    cudaGetSymbolAddress((void**)&Wlp, g_Wl);
    cudaGetSymbolAddress((void**)&Ohp, g_Oh);
    cudaGetSymbolAddress((void**)&Olp, g_Ol);

    cudaFuncSetAttribute(gemm_mm<0>, cudaFuncAttributeMaxDynamicSharedMemorySize, GEMM_SMEM);
    cudaFuncSetAttribute(gemm_mm<1>, cudaFuncAttributeMaxDynamicSharedMemorySize, GEMM_SMEM);
    cudaFuncSetAttribute(attn_kernel, cudaFuncAttributeMaxDynamicSharedMemorySize, 65536);

    const int nAct4 = (M_ * D_) / 4;
    const int nW4   = (D_ * D_) / 4;
    dim3 gg(D_ / 128, M_ / 128);       // (8, 64)

    // Q projection
    split_bf16_kernel<<<nAct4 / 256, 256>>>(query, Ahp, Alp, nAct4);
    split_bf16_kernel<<<nW4 / 256, 256>>>(wq, Whp, Wlp, nW4);
    gemm_mm<1><<<gg, 256, GEMM_SMEM>>>(Ahp, Alp, Whp, Wlp, nullptr, Qp);
    // K projection
    split_bf16_kernel<<<nAct4 / 256, 256>>>(key, Ahp, Alp, nAct4);
    split_bf16_kernel<<<nW4 / 256, 256>>>(wk, Whp, Wlp, nW4);
    gemm_mm<1><<<gg, 256, GEMM_SMEM>>>(Ahp, Alp, Whp, Wlp, nullptr, Kp);
    // V projection
    split_bf16_kernel<<<nAct4 / 256, 256>>>(value, Ahp, Alp, nAct4);
    split_bf16_kernel<<<nW4 / 256, 256>>>(wv, Whp, Wlp, nW4);
    gemm_mm<1><<<gg, 256, GEMM_SMEM>>>(Ahp, Alp, Whp, Wlp, nullptr, Vp);

    // attention (writes bf16 hi/lo O)
    attn_kernel<<<dim3(S_ / 64, B_ * H_), 256, 65536>>>(Qp, Kp, Vp, Ohp, Olp);

    // output projection + bias
    split_bf16_kernel<<<nW4 / 256, 256>>>(wo, Whp, Wlp, nW4);
    gemm_mm<0><<<gg, 256, GEMM_SMEM>>>(Ohp, Olp, Whp, Wlp, bo, out);
}

// round 8
// speedup vs baseline: 1.2771x; 1.0001x over previous
#include <cuda_runtime.h>
#include <cuda_bf16.h>
#include <math.h>

typedef unsigned long long ull_t;
typedef unsigned int u32;

#define B_  4
#define S_  2048
#define D_  1024
#define H_  16
#define HD_ 64
#define M_  (B_*S_)   // 8192

// ---------------- scratch (__device__ globals: allocation-free rule) ----------
__device__ float g_Q[(size_t)B_*H_*S_*HD_];
__device__ float g_K[(size_t)B_*H_*S_*HD_];
__device__ float g_V[(size_t)B_*H_*S_*HD_];
__device__ __nv_bfloat16 g_Ah[(size_t)M_*D_];
__device__ __nv_bfloat16 g_Al[(size_t)M_*D_];
__device__ __nv_bfloat16 g_Wh[(size_t)D_*D_];
__device__ __nv_bfloat16 g_Wl[(size_t)D_*D_];
__device__ __nv_bfloat16 g_Oh[(size_t)M_*D_];
__device__ __nv_bfloat16 g_Ol[(size_t)M_*D_];

// ---------------- packed f32x2 helpers (attention kernel) --------------------
__device__ __forceinline__ void fma2(ull_t& d, ull_t a, ull_t b) {
    asm("fma.rn.f32x2 %0, %1, %2, %0;" : "+l"(d) : "l"(a), "l"(b));
}
__device__ __forceinline__ ull_t dup2(float x) {
    ull_t r; asm("mov.b64 %0, {%1, %1};" : "=l"(r) : "f"(x)); return r;
}
__device__ __forceinline__ ull_t pack2(float x, float y) {
    ull_t r; asm("mov.b64 %0, {%1, %2};" : "=l"(r) : "f"(x), "f"(y)); return r;
}
__device__ __forceinline__ ull_t mul2(ull_t a, ull_t b) {
    ull_t r; asm("mul.rn.f32x2 %0, %1, %2;" : "=l"(r) : "l"(a), "l"(b)); return r;
}
__device__ __forceinline__ float2 unpk2(ull_t a) {
    float2 r; asm("mov.b64 {%0, %1}, %2;" : "=f"(r.x), "=f"(r.y) : "l"(a)); return r;
}

// ---------------- baseline-PTX tensor-core helpers (sm_80+, works on sm_103) --
__device__ __forceinline__ u32 smem_u32(const void* p) {
    u32 a; asm("{ .reg .u64 t; cvta.to.shared.u64 t, %1; cvt.u32.u64 %0, t; }" : "=r"(a) : "l"(p));
    return a;
}
__device__ __forceinline__ void ldm_x4(u32* r, u32 addr) {
    asm volatile("ldmatrix.sync.aligned.m8n8.x4.shared.b16 {%0,%1,%2,%3}, [%4];"
        : "=r"(r[0]), "=r"(r[1]), "=r"(r[2]), "=r"(r[3]) : "r"(addr));
}
__device__ __forceinline__ void mma16816(float* d, const u32* a, u32 b0, u32 b1) {
    asm volatile("mma.sync.aligned.m16n8k16.row.col.f32.bf16.bf16.f32 "
        "{%0,%1,%2,%3}, {%4,%5,%6,%7}, {%8,%9}, {%0,%1,%2,%3};"
        : "+f"(d[0]), "+f"(d[1]), "+f"(d[2]), "+f"(d[3])
        : "r"(a[0]), "r"(a[1]), "r"(a[2]), "r"(a[3]), "r"(b0), "r"(b1));
}
#define CP_ASYNC(dst, src) asm volatile("cp.async.cg.shared.global [%0], [%1], 16;" :: "r"(dst), "l"(src) : "memory")
#define CP_COMMIT()  asm volatile("cp.async.commit_group;" ::: "memory")
#define CP_WAIT(n)   asm volatile("cp.async.wait_group %0;" :: "n"(n) : "memory")

// =====================================================================
// fp32 -> bf16 hi/lo split (x = hi + lo + O(2^-16 x))
// =====================================================================
__global__ void split_bf16_kernel(const float* __restrict__ x,
                                  __nv_bfloat16* __restrict__ hi,
                                  __nv_bfloat16* __restrict__ lo, int n4)
{
    int i = blockIdx.x * blockDim.x + threadIdx.x;
    if (i >= n4) return;
    float4 v = ((const float4*)x)[i];
    float f[4] = { v.x, v.y, v.z, v.w };
    union { __nv_bfloat16 b[4]; uint2 u; } Hh, Ll;
    #pragma unroll
    for (int j = 0; j < 4; j++) {
        __nv_bfloat16 h = __float2bfloat16(f[j]);
        Hh.b[j] = h;
        Ll.b[j] = __float2bfloat16(f[j] - __bfloat162float(h));
    }
    ((uint2*)hi)[i] = Hh.u;
    ((uint2*)lo)[i] = Ll.u;
}

// =====================================================================
// HMMA GEMM (mma.sync bf16, hi/lo 3-pass): C[m][n] = sum_k A[m][k]*W[n][k]
// CTA 128x128, 8 warps (2m x 4n), warp tile 64x32, k-chunk 32, cp.async DB.
// MODE 0: C=[M_,D_]+bias. MODE 1: C->[B,H,S,HD].
// =====================================================================
#define SROW 40                      // bf16 per smem row (32 data + 8 pad)
#define TILEB (128 * SROW * 2)       // 10240 B per tile
#define BUFB  (4 * TILEB)            // Ah,Al,Bh,Bl : 40960 B
#define GEMM_SMEM (2 * BUFB + 128)   // 82048 B

template<int MODE>
__global__ __launch_bounds__(256, 1)
void gemm_mm(const __nv_bfloat16* __restrict__ Ah, const __nv_bfloat16* __restrict__ Al,
             const __nv_bfloat16* __restrict__ Bh, const __nv_bfloat16* __restrict__ Bl,
             const float* __restrict__ bias, float* __restrict__ C)
{
    extern __shared__ char smem[];
    const u32 sbase = (smem_u32(smem) + 127) & ~127u;

    const int t = threadIdx.x;
    const int l = t & 31;
    const int warp = t >> 5;
    const int wm = warp >> 2, wn = warp & 3;
    const int m0 = blockIdx.y * 128;
    const int n0 = blockIdx.x * 128;

    const __nv_bfloat16* gp0 = Ah + (size_t)m0 * D_;
    const __nv_bfloat16* gp1 = Al + (size_t)m0 * D_;
    const __nv_bfloat16* gp2 = Bh + (size_t)n0 * D_;
    const __nv_bfloat16* gp3 = Bl + (size_t)n0 * D_;

    // per-lane ldmatrix offsets
    const u32 aoff = ((u32)(wm*64 + ((l & 7) + ((l >> 3) & 1) * 8)) * SROW + ((l >> 4) * 8)) * 2;
    const u32 boff = ((u32)(wn*32 + ((l & 7) + ((l >> 4) & 1) * 8)) * SROW + (((l >> 3) & 1) * 8)) * 2;

    float acc[4][4][4];
    #pragma unroll
    for (int i = 0; i < 4; i++)
        #pragma unroll
        for (int j = 0; j < 4; j++)
            #pragma unroll
            for (int q = 0; q < 4; q++) acc[i][j][q] = 0.f;

    const int r_ld = (t + 0) >> 2;      // base row for this thread's copies
    const int c_ld = t & 3;

    // chunk copy: 4 tiles x 128 rows x 64B ; thread does 8 x 16B cp.async
    auto cp_chunk = [&](int kc, int bufsel) {
        u32 db = sbase + (u32)bufsel * BUFB;
        #pragma unroll
        for (int i = 0; i < 8; i++) {
            int idx = t + (i & 1) * 256;        // 0..511 within tile
            int r = idx >> 2, c = idx & 3;
            size_t go = (size_t)r * D_ + kc + c * 8;
            u32 dst = db + (u32)(i >> 1) * TILEB + (u32)(r * SROW + c * 8) * 2;
            const __nv_bfloat16* src = (i < 2) ? gp0 : (i < 4) ? gp1 : (i < 6) ? gp2 : gp3;
            CP_ASYNC(dst, src + go);
        }
    };
    (void)r_ld; (void)c_ld;

    cp_chunk(0, 0);
    CP_COMMIT();

    const int NCH = D_ / 32;   // 32
    for (int kt = 0; kt < NCH; kt++) {
        int buf = kt & 1;
        if (kt + 1 < NCH) {
            cp_chunk((kt + 1) * 32, buf ^ 1);
            CP_COMMIT();
            CP_WAIT(1);
        } else {
            CP_WAIT(0);
        }
        __syncthreads();

        u32 aH = sbase + (u32)buf * BUFB;
        u32 bH = aH + 2 * TILEB;

        #pragma unroll
        for (int ks = 0; ks < 2; ks++) {
            u32 ah[4][4], al[4][4], bh[2][4], bl[2][4];
            #pragma unroll
            for (int mt = 0; mt < 4; mt++) {
                u32 ad = aH + aoff + (u32)(mt * 16 * SROW + ks * 16) * 2;
                ldm_x4(ah[mt], ad);
                ldm_x4(al[mt], ad + TILEB);
            }
            #pragma unroll
            for (int nt = 0; nt < 2; nt++) {
                u32 bd = bH + boff + (u32)(nt * 16 * SROW + ks * 16) * 2;
                ldm_x4(bh[nt], bd);
                ldm_x4(bl[nt], bd + TILEB);
            }
            #pragma unroll
            for (int mt = 0; mt < 4; mt++)
                #pragma unroll
                for (int j = 0; j < 4; j++) {
                    u32 h0 = bh[j >> 1][(j & 1) * 2], h1 = bh[j >> 1][(j & 1) * 2 + 1];
                    u32 l0 = bl[j >> 1][(j & 1) * 2], l1 = bl[j >> 1][(j & 1) * 2 + 1];
                    mma16816(acc[mt][j], ah[mt], h0, h1);   // Ah*Bh
                    mma16816(acc[mt][j], al[mt], h0, h1);   // Al*Bh
                    mma16816(acc[mt][j], ah[mt], l0, l1);   // Ah*Bl
                }
        }
        __syncthreads();
    }

    // epilogue: lane l holds rows (mt*16 + l/4, +8), cols (j*8 + (l%4)*2, +1)
    const int r0 = l >> 2, cp2 = (l & 3) * 2;
    #pragma unroll
    for (int mt = 0; mt < 4; mt++)
        #pragma unroll
        for (int j = 0; j < 4; j++) {
            int m = m0 + wm * 64 + mt * 16 + r0;
            int n = n0 + wn * 32 + j * 8 + cp2;
            if (MODE == 0) {
                float2 bb = *(const float2*)&bias[n];
                *(float2*)&C[(size_t)m * D_ + n] =
                    make_float2(acc[mt][j][0] + bb.x, acc[mt][j][1] + bb.y);
                *(float2*)&C[(size_t)(m + 8) * D_ + n] =
                    make_float2(acc[mt][j][2] + bb.x, acc[mt][j][3] + bb.y);
            } else {
                int h = n >> 6, d = n & 63;
                int b = m >> 11, s = m & 2047;
                float* dst = &C[(((size_t)(b * H_ + h)) * S_ + s) * HD_ + d];
                *(float2*)dst = make_float2(acc[mt][j][0], acc[mt][j][1]);
                *(float2*)(dst + 8 * HD_) = make_float2(acc[mt][j][2], acc[mt][j][3]);
            }
        }
}

// =====================================================================
// Flash attention fp32 (proven scalar core); epilogue writes bf16 hi/lo O
// =====================================================================
__global__ __launch_bounds__(256, 2)
void attn_kernel(const float* __restrict__ Q, const float* __restrict__ Kg,
                 const float* __restrict__ Vg,
                 __nv_bfloat16* __restrict__ Oh, __nv_bfloat16* __restrict__ Ol)
{
    extern __shared__ float sm[];
    float* Qs = sm;            // [64][64]
    float* Ks = sm + 4096;     // [64][64]
    float* Vs = sm + 8192;     // [64][64]
    float* Ps = sm + 12288;    // [64][64]

    int tid = threadIdx.x;
    int tx = tid & 15, ty = tid >> 4;
    int bh = blockIdx.y;
    int q0 = blockIdx.x * 64;

    const float* Qb = Q + ((size_t)bh * S_ + q0) * HD_;
    const float* Kb = Kg + (size_t)bh * S_ * HD_;
    const float* Vb = Vg + (size_t)bh * S_ * HD_;

    #pragma unroll
    for (int it = 0; it < 4; it++) {
        int i = tid + it * 256;
        int r = i >> 4, c = (i & 15) << 2;
        *(float4*)&Qs[r * 64 + c] = *(const float4*)&Qb[r * HD_ + c];
    }

    ull_t acc[4][4];
    #pragma unroll
    for (int i = 0; i < 4; i++)
        #pragma unroll
        for (int j = 0; j < 4; j++) acc[i][j] = 0ull;
    float mi[4] = { -1e30f, -1e30f, -1e30f, -1e30f };
    float li[4] = { 0.f, 0.f, 0.f, 0.f };

    for (int kb = 0; kb < S_ / 64; kb++) {
        const float* Kt = Kb + (size_t)kb * 64 * HD_;
        const float* Vt = Vb + (size_t)kb * 64 * HD_;

        __syncthreads();
        #pragma unroll
        for (int it = 0; it < 4; it++) {
            int i = tid + it * 256;
            int r = i >> 4, c = (i & 15) << 2;
            *(float4*)&Ks[r * 64 + c] = *(const float4*)&Kt[r * HD_ + c];
            *(float4*)&Vs[r * 64 + c] = *(const float4*)&Vt[r * HD_ + c];
        }
        __syncthreads();

        ull_t s2[4][4];
        #pragma unroll
        for (int i = 0; i < 4; i++)
            #pragma unroll
            for (int j = 0; j < 4; j++) s2[i][j] = 0ull;

        #pragma unroll 4
        for (int dg = 0; dg < 16; dg++) {
            int dd = ((dg + tx) & 15) << 2;
            union { float4 f; ull_t u[2]; } qf[4], kf[4];
            #pragma unroll
            for (int i = 0; i < 4; i++) qf[i].f = *(const float4*)&Qs[(ty*4+i)*64 + dd];
            #pragma unroll
            for (int j = 0; j < 4; j++) kf[j].f = *(const float4*)&Ks[(tx*4+j)*64 + dd];
            #pragma unroll
            for (int i = 0; i < 4; i++)
                #pragma unroll
                for (int j = 0; j < 4; j++) {
                    fma2(s2[i][j], qf[i].u[0], kf[j].u[0]);
                    fma2(s2[i][j], qf[i].u[1], kf[j].u[1]);
                }
        }

        float p[4][4];
        #pragma unroll
        for (int i = 0; i < 4; i++) {
            float srow[4];
            #pragma unroll
            for (int j = 0; j < 4; j++) {
                float2 v = unpk2(s2[i][j]);
                srow[j] = (v.x + v.y) * 0.125f;
            }
            float rm = fmaxf(fmaxf(srow[0], srow[1]), fmaxf(srow[2], srow[3]));
            rm = fmaxf(rm, __shfl_xor_sync(0xffffffffu, rm, 1));
            rm = fmaxf(rm, __shfl_xor_sync(0xffffffffu, rm, 2));
            rm = fmaxf(rm, __shfl_xor_sync(0xffffffffu, rm, 4));
            rm = fmaxf(rm, __shfl_xor_sync(0xffffffffu, rm, 8));
            float mnew = fmaxf(mi[i], rm);
            float corr = __expf(mi[i] - mnew);
            mi[i] = mnew;
            float rs = 0.f;
            #pragma unroll
            for (int j = 0; j < 4; j++) { p[i][j] = __expf(srow[j] - mnew); rs += p[i][j]; }
            rs += __shfl_xor_sync(0xffffffffu, rs, 1);
            rs += __shfl_xor_sync(0xffffffffu, rs, 2);
            rs += __shfl_xor_sync(0xffffffffu, rs, 4);
            rs += __shfl_xor_sync(0xffffffffu, rs, 8);
            li[i] = li[i] * corr + rs;
            ull_t c2 = dup2(corr);
            #pragma unroll
            for (int j = 0; j < 4; j++) acc[i][j] = mul2(acc[i][j], c2);
        }
        #pragma unroll
        for (int i = 0; i < 4; i++)
            *(float4*)&Ps[(ty*4+i)*64 + tx*4] = make_float4(p[i][0], p[i][1], p[i][2], p[i][3]);
        __syncthreads();

        #pragma unroll 4
        for (int cg = 0; cg < 16; cg++) {
            int cc = ((cg + tx) & 15) << 2;
            union { float4 f; ull_t u[2]; } pf[4];
            #pragma unroll
            for (int i = 0; i < 4; i++) pf[i].f = *(const float4*)&Ps[(ty*4+i)*64 + cc];
            float4 v0 = *(const float4*)&Vs[(cc+0)*64 + tx*4];
            float4 v1 = *(const float4*)&Vs[(cc+1)*64 + tx*4];
            float4 v2 = *(const float4*)&Vs[(cc+2)*64 + tx*4];
            float4 v3 = *(const float4*)&Vs[(cc+3)*64 + tx*4];
            ull_t va[4] = { pack2(v0.x,v1.x), pack2(v0.y,v1.y), pack2(v0.z,v1.z), pack2(v0.w,v1.w) };
            ull_t vb[4] = { pack2(v2.x,v3.x), pack2(v2.y,v3.y), pack2(v2.z,v3.z), pack2(v2.w,v3.w) };
            #pragma unroll
            for (int i = 0; i < 4; i++)
                #pragma unroll
                for (int j = 0; j < 4; j++) {
                    fma2(acc[i][j], pf[i].u[0], va[j]);
                    fma2(acc[i][j], pf[i].u[1], vb[j]);
                }
        }
    }

    // epilogue: normalize + write bf16 hi/lo into [M_, D_] layout
    int b = bh >> 4, h = bh & 15;
    #pragma unroll
    for (int i = 0; i < 4; i++) {
        float inv = 1.0f / li[i];
        int s = q0 + ty * 4 + i;
        size_t base = ((size_t)(b * S_ + s)) * D_ + h * HD_ + tx * 4;
        union { __nv_bfloat16 bb[4]; uint2 u; } HH, LL;
        #pragma unroll
        for (int j = 0; j < 4; j++) {
            float2 v = unpk2(acc[i][j]);
            float o = (v.x + v.y) * inv;
            __nv_bfloat16 hv = __float2bfloat16(o);
            HH.bb[j] = hv;
            LL.bb[j] = __float2bfloat16(o - __bfloat162float(hv));
        }
        *(uint2*)&Oh[base] = HH.u;
        *(uint2*)&Ol[base] = LL.u;
    }
}

// =====================================================================
extern "C" void kernel_launch(void* const* d_in, const int* in_sizes, int n_in,
                              void* d_out, int out_size)
{
    const float* query = (const float*)d_in[0];
    const float* key   = (const float*)d_in[1];
    const float* value = (const float*)d_in[2];
    const float* wq    = (const float*)d_in[3];
    const float* wk    = (const float*)d_in[4];
    const float* wv    = (const float*)d_in[5];
    const float* wo    = (const float*)d_in[6];
    const float* bo    = (const float*)d_in[7];
    float* out = (float*)d_out;

    float *Qp, *Kp, *Vp;
    __nv_bfloat16 *Ahp, *Alp, *Whp, *Wlp, *Ohp, *Olp;
    cudaGetSymbolAddress((void**)&Qp, g_Q);
    cudaGetSymbolAddress((void**)&Kp, g_K);
    cudaGetSymbolAddress((void**)&Vp, g_V);
    cudaGetSymbolAddress((void**)&Ahp, g_Ah);
    cudaGetSymbolAddress((void**)&Alp, g_Al);
    cudaGetSymbolAddress((void**)&Whp, g_Wh);
    cudaGetSymbolAddress((void**)&Wlp, g_Wl);
    cudaGetSymbolAddress((void**)&Ohp, g_Oh);
    cudaGetSymbolAddress((void**)&Olp, g_Ol);

    cudaFuncSetAttribute(gemm_mm<0>, cudaFuncAttributeMaxDynamicSharedMemorySize, GEMM_SMEM);
    cudaFuncSetAttribute(gemm_mm<1>, cudaFuncAttributeMaxDynamicSharedMemorySize, GEMM_SMEM);
    cudaFuncSetAttribute(attn_kernel, cudaFuncAttributeMaxDynamicSharedMemorySize, 65536);

    const int nAct4 = (M_ * D_) / 4;
    const int nW4   = (D_ * D_) / 4;
    dim3 gg(D_ / 128, M_ / 128);       // (8, 64)

    // Q projection
    split_bf16_kernel<<<nAct4 / 256, 256>>>(query, Ahp, Alp, nAct4);
    split_bf16_kernel<<<nW4 / 256, 256>>>(wq, Whp, Wlp, nW4);
    gemm_mm<1><<<gg, 256, GEMM_SMEM>>>(Ahp, Alp, Whp, Wlp, nullptr, Qp);
    // K projection
    split_bf16_kernel<<<nAct4 / 256, 256>>>(key, Ahp, Alp, nAct4);
    split_bf16_kernel<<<nW4 / 256, 256>>>(wk, Whp, Wlp, nW4);
    gemm_mm<1><<<gg, 256, GEMM_SMEM>>>(Ahp, Alp, Whp, Wlp, nullptr, Kp);
    // V projection
    split_bf16_kernel<<<nAct4 / 256, 256>>>(value, Ahp, Alp, nAct4);
    split_bf16_kernel<<<nW4 / 256, 256>>>(wv, Whp, Wlp, nW4);
    gemm_mm<1><<<gg, 256, GEMM_SMEM>>>(Ahp, Alp, Whp, Wlp, nullptr, Vp);

    // attention (writes bf16 hi/lo O)
    attn_kernel<<<dim3(S_ / 64, B_ * H_), 256, 65536>>>(Qp, Kp, Vp, Ohp, Olp);

    // output projection + bias
    split_bf16_kernel<<<nW4 / 256, 256>>>(wo, Whp, Wlp, nW4);
    gemm_mm<0><<<gg, 256, GEMM_SMEM>>>(Ohp, Olp, Whp, Wlp, bo, out);
}